// round 1
// baseline (speedup 1.0000x reference)
#include <cuda_runtime.h>
#include <cstdint>

#define N_FEAT 8
#define E_FEAT 4
#define NUM_IN 25   // 2*(8+2)+4+1
#define NUM_OUT 20  // 2*8+4

typedef unsigned long long u64;

__device__ __forceinline__ u64 pk2(float lo, float hi) {
    u64 r;
    asm("mov.b64 %0, {%1, %2};" : "=l"(r) : "f"(lo), "f"(hi));
    return r;
}
__device__ __forceinline__ void upk2(u64 v, float& lo, float& hi) {
    asm("mov.b64 {%0, %1}, %2;" : "=f"(lo), "=f"(hi) : "l"(v));
}
__device__ __forceinline__ u64 ffma2(u64 a, u64 b, u64 c) {
    u64 d;
    asm("fma.rn.f32x2 %0, %1, %2, %3;" : "=l"(d) : "l"(a), "l"(b), "l"(c));
    return d;
}
__device__ __forceinline__ u64 relu2(u64 v) {
    float lo, hi;
    upk2(v, lo, hi);
    return pk2(fmaxf(lo, 0.0f), fmaxf(hi, 0.0f));
}

// Shared weight layout (all pre-splatted to {w,w} for f32x2):
// [0,625)    W1 (25x25 row-major: W1[j*25+k])
// [625,650)  b1
// [650,1150) W2 (20x25 row-major: W2[i*25+k])
// [1150,1170) b2
#define SMEM_TOTAL 1170

__global__ void __launch_bounds__(256)
edge_mlp_kernel(const float* __restrict__ r,
                const float* __restrict__ a_data,
                const float* __restrict__ a_material,
                const float* __restrict__ a_influx,
                const float* __restrict__ b_data,
                const float* __restrict__ b_material,
                const float* __restrict__ b_influx,
                const float* __restrict__ e_data,
                const float* __restrict__ W1,
                const float* __restrict__ b1,
                const float* __restrict__ W2,
                const float* __restrict__ b2,
                float* __restrict__ out,
                int E)
{
    __shared__ u64 sAll[SMEM_TOTAL];
    u64* sW1 = sAll;
    u64* sB1 = sAll + 625;
    u64* sW2 = sAll + 650;
    u64* sB2 = sAll + 1150;

    // Cooperative splat-load of all weights into shared.
    for (int i = threadIdx.x; i < SMEM_TOTAL; i += blockDim.x) {
        float v;
        if (i < 625)        v = W1[i];
        else if (i < 650)   v = b1[i - 625];
        else if (i < 1150)  v = W2[i - 650];
        else                v = b2[i - 1150];
        sAll[i] = pk2(v, v);
    }

    int pair = blockIdx.x * blockDim.x + threadIdx.x;
    int e0 = pair * 2;

    __syncthreads();

    if (e0 >= E) return;
    bool have_e1 = (e0 + 1 < E);
    int e1 = have_e1 ? (e0 + 1) : e0;

    // ---- Gather & pack inputs: xv[k] = {x_e0[k], x_e1[k]} ----
    const float4* ad4 = reinterpret_cast<const float4*>(a_data);
    const float4* bd4 = reinterpret_cast<const float4*>(b_data);
    const float4* ed4 = reinterpret_cast<const float4*>(e_data);

    u64 xv[NUM_IN];
    xv[0] = pk2(r[e0], r[e1]);
    {
        float4 p = ad4[2 * e0], q = ad4[2 * e1];
        xv[1] = pk2(p.x, q.x); xv[2] = pk2(p.y, q.y);
        xv[3] = pk2(p.z, q.z); xv[4] = pk2(p.w, q.w);
        p = ad4[2 * e0 + 1];  q = ad4[2 * e1 + 1];
        xv[5] = pk2(p.x, q.x); xv[6] = pk2(p.y, q.y);
        xv[7] = pk2(p.z, q.z); xv[8] = pk2(p.w, q.w);
    }
    xv[9]  = pk2(a_material[e0], a_material[e1]);
    xv[10] = pk2(a_influx[e0],   a_influx[e1]);
    {
        float4 p = bd4[2 * e0], q = bd4[2 * e1];
        xv[11] = pk2(p.x, q.x); xv[12] = pk2(p.y, q.y);
        xv[13] = pk2(p.z, q.z); xv[14] = pk2(p.w, q.w);
        p = bd4[2 * e0 + 1];  q = bd4[2 * e1 + 1];
        xv[15] = pk2(p.x, q.x); xv[16] = pk2(p.y, q.y);
        xv[17] = pk2(p.z, q.z); xv[18] = pk2(p.w, q.w);
    }
    xv[19] = pk2(b_material[e0], b_material[e1]);
    xv[20] = pk2(b_influx[e0],   b_influx[e1]);
    {
        float4 p = ed4[e0], q = ed4[e1];
        xv[21] = pk2(p.x, q.x); xv[22] = pk2(p.y, q.y);
        xv[23] = pk2(p.z, q.z); xv[24] = pk2(p.w, q.w);
    }

    // ---- Layer 1: y = relu(W1 @ x + b1), 25x25 ----
    u64 y[NUM_IN];
    #pragma unroll
    for (int j = 0; j < NUM_IN; j++) y[j] = sB1[j];

    #pragma unroll
    for (int k = 0; k < NUM_IN; k++) {
        u64 xk = xv[k];
        #pragma unroll
        for (int j = 0; j < NUM_IN; j++) {
            y[j] = ffma2(sW1[j * NUM_IN + k], xk, y[j]);
        }
    }
    #pragma unroll
    for (int j = 0; j < NUM_IN; j++) y[j] = relu2(y[j]);

    // ---- Layer 2: z = relu(W2 @ y + b2), 20x25 ----
    u64 z[NUM_OUT];
    #pragma unroll
    for (int i = 0; i < NUM_OUT; i++) z[i] = sB2[i];

    #pragma unroll
    for (int k = 0; k < NUM_IN; k++) {
        u64 yk = y[k];
        #pragma unroll
        for (int i = 0; i < NUM_OUT; i++) {
            z[i] = ffma2(sW2[i * NUM_IN + k], yk, z[i]);
        }
    }

    float zl[NUM_OUT], zh[NUM_OUT];
    #pragma unroll
    for (int i = 0; i < NUM_OUT; i++) {
        upk2(z[i], zl[i], zh[i]);
        zl[i] = fmaxf(zl[i], 0.0f);
        zh[i] = fmaxf(zh[i], 0.0f);
    }

    // ---- Scatter to the three concatenated output blocks ----
    // block0: out[0 .. 8E)        = z[:,0:8]   row-major
    // block1: out[8E .. 16E)      = z[:,8:16]
    // block2: out[16E .. 20E)     = z[:,16:20]
    float4* ov = reinterpret_cast<float4*>(out);
    long Ef4_b1 = 2L * (long)E;   // start of block1 in float4 units
    long Ef4_b2 = 4L * (long)E;   // start of block2 in float4 units

    ov[2L * e0]              = make_float4(zl[0],  zl[1],  zl[2],  zl[3]);
    ov[2L * e0 + 1]          = make_float4(zl[4],  zl[5],  zl[6],  zl[7]);
    ov[Ef4_b1 + 2L * e0]     = make_float4(zl[8],  zl[9],  zl[10], zl[11]);
    ov[Ef4_b1 + 2L * e0 + 1] = make_float4(zl[12], zl[13], zl[14], zl[15]);
    ov[Ef4_b2 + e0]          = make_float4(zl[16], zl[17], zl[18], zl[19]);

    if (have_e1) {
        ov[2L * e1]              = make_float4(zh[0],  zh[1],  zh[2],  zh[3]);
        ov[2L * e1 + 1]          = make_float4(zh[4],  zh[5],  zh[6],  zh[7]);
        ov[Ef4_b1 + 2L * e1]     = make_float4(zh[8],  zh[9],  zh[10], zh[11]);
        ov[Ef4_b1 + 2L * e1 + 1] = make_float4(zh[12], zh[13], zh[14], zh[15]);
        ov[Ef4_b2 + e1]          = make_float4(zh[16], zh[17], zh[18], zh[19]);
    }
}

extern "C" void kernel_launch(void* const* d_in, const int* in_sizes, int n_in,
                              void* d_out, int out_size)
{
    const float* r          = (const float*)d_in[0];
    const float* a_data     = (const float*)d_in[1];
    const float* a_material = (const float*)d_in[2];
    const float* a_influx   = (const float*)d_in[3];
    const float* b_data     = (const float*)d_in[4];
    const float* b_material = (const float*)d_in[5];
    const float* b_influx   = (const float*)d_in[6];
    const float* e_data     = (const float*)d_in[7];
    const float* W1         = (const float*)d_in[8];
    const float* b1         = (const float*)d_in[9];
    const float* W2         = (const float*)d_in[10];
    const float* b2         = (const float*)d_in[11];
    float* out = (float*)d_out;

    int E = in_sizes[0];
    int pairs = (E + 1) / 2;
    int threads = 256;
    int blocks = (pairs + threads - 1) / threads;

    edge_mlp_kernel<<<blocks, threads>>>(r, a_data, a_material, a_influx,
                                         b_data, b_material, b_influx, e_data,
                                         W1, b1, W2, b2, out, E);
}

// round 2
// speedup vs baseline: 1.1537x; 1.1537x over previous
#include <cuda_runtime.h>
#include <cstdint>

#define N_FEAT 8
#define E_FEAT 4
#define NUM_IN 25   // 2*(8+2)+4+1
#define NUM_OUT 20  // 2*8+4
#define ROW_PAD 26  // pad rows to even # of u64 so k-pairs are 16B aligned

typedef unsigned long long u64;

__device__ __forceinline__ u64 pk2(float lo, float hi) {
    u64 r;
    asm("mov.b64 %0, {%1, %2};" : "=l"(r) : "f"(lo), "f"(hi));
    return r;
}
__device__ __forceinline__ void upk2(u64 v, float& lo, float& hi) {
    asm("mov.b64 {%0, %1}, %2;" : "=f"(lo), "=f"(hi) : "l"(v));
}
__device__ __forceinline__ u64 ffma2(u64 a, u64 b, u64 c) {
    u64 d;
    asm("fma.rn.f32x2 %0, %1, %2, %3;" : "=l"(d) : "l"(a), "l"(b), "l"(c));
    return d;
}
__device__ __forceinline__ u64 relu2(u64 v) {
    float lo, hi;
    upk2(v, lo, hi);
    return pk2(fmaxf(lo, 0.0f), fmaxf(hi, 0.0f));
}

// Shared layout (u64 elements, all weights pre-splatted {w,w}):
//   sW1: 25 rows x 26  -> [0, 650)
//   sB1: 25            -> [650, 675)
//   sW2: 20 rows x 26  -> [676, 1196)   (676 even => rows 16B aligned)
//   sB2: 20            -> [1196, 1216)
#define OFF_W1 0
#define OFF_B1 650
#define OFF_W2 676
#define OFF_B2 1196
#define SMEM_TOTAL 1216

// Layer-1 partial: compute y[j] for j in [J0,J1) over all 25 inputs.
template <int J0, int J1>
__device__ __forceinline__ void layer1_chunk(const u64* __restrict__ sAll,
                                             const u64 (&xv)[NUM_IN],
                                             u64 (&y)[NUM_IN]) {
    u64 acc[J1 - J0];
    #pragma unroll
    for (int j = J0; j < J1; j++) acc[j - J0] = sAll[OFF_B1 + j];

    #pragma unroll
    for (int kp = 0; kp < 12; kp++) {
        u64 x0 = xv[2 * kp], x1 = xv[2 * kp + 1];
        #pragma unroll
        for (int j = J0; j < J1; j++) {
            const ulonglong2 w =
                *reinterpret_cast<const ulonglong2*>(&sAll[OFF_W1 + j * ROW_PAD + 2 * kp]);
            acc[j - J0] = ffma2(w.x, x0, acc[j - J0]);
            acc[j - J0] = ffma2(w.y, x1, acc[j - J0]);
        }
    }
    // leftover k = 24
    {
        u64 x24 = xv[24];
        #pragma unroll
        for (int j = J0; j < J1; j++)
            acc[j - J0] = ffma2(sAll[OFF_W1 + j * ROW_PAD + 24], x24, acc[j - J0]);
    }
    #pragma unroll
    for (int j = J0; j < J1; j++) y[j] = relu2(acc[j - J0]);
}

// Layer-2 partial: compute z[i] for i in [I0,I1), relu'd halves into zl/zh.
template <int I0, int I1>
__device__ __forceinline__ void layer2_chunk(const u64* __restrict__ sAll,
                                             const u64 (&y)[NUM_IN],
                                             float (&zl)[I1 - I0],
                                             float (&zh)[I1 - I0]) {
    u64 acc[I1 - I0];
    #pragma unroll
    for (int i = I0; i < I1; i++) acc[i - I0] = sAll[OFF_B2 + i];

    #pragma unroll
    for (int kp = 0; kp < 12; kp++) {
        u64 y0 = y[2 * kp], y1 = y[2 * kp + 1];
        #pragma unroll
        for (int i = I0; i < I1; i++) {
            const ulonglong2 w =
                *reinterpret_cast<const ulonglong2*>(&sAll[OFF_W2 + i * ROW_PAD + 2 * kp]);
            acc[i - I0] = ffma2(w.x, y0, acc[i - I0]);
            acc[i - I0] = ffma2(w.y, y1, acc[i - I0]);
        }
    }
    {
        u64 y24 = y[24];
        #pragma unroll
        for (int i = I0; i < I1; i++)
            acc[i - I0] = ffma2(sAll[OFF_W2 + i * ROW_PAD + 24], y24, acc[i - I0]);
    }
    #pragma unroll
    for (int i = I0; i < I1; i++) {
        float lo, hi;
        upk2(acc[i - I0], lo, hi);
        zl[i - I0] = fmaxf(lo, 0.0f);
        zh[i - I0] = fmaxf(hi, 0.0f);
    }
}

__global__ void __launch_bounds__(256, 2)
edge_mlp_kernel(const float* __restrict__ r,
                const float* __restrict__ a_data,
                const float* __restrict__ a_material,
                const float* __restrict__ a_influx,
                const float* __restrict__ b_data,
                const float* __restrict__ b_material,
                const float* __restrict__ b_influx,
                const float* __restrict__ e_data,
                const float* __restrict__ W1,
                const float* __restrict__ b1,
                const float* __restrict__ W2,
                const float* __restrict__ b2,
                float* __restrict__ out,
                int E)
{
    __shared__ __align__(16) u64 sAll[SMEM_TOTAL];

    // Cooperative splat-load of weights into padded shared layout.
    for (int i = threadIdx.x; i < 625; i += blockDim.x) {
        int row = i / NUM_IN, col = i % NUM_IN;
        sAll[OFF_W1 + row * ROW_PAD + col] = pk2(W1[i], W1[i]);
    }
    for (int i = threadIdx.x; i < 500; i += blockDim.x) {
        int row = i / NUM_IN, col = i % NUM_IN;
        sAll[OFF_W2 + row * ROW_PAD + col] = pk2(W2[i], W2[i]);
    }
    if (threadIdx.x < NUM_IN)  sAll[OFF_B1 + threadIdx.x] = pk2(b1[threadIdx.x], b1[threadIdx.x]);
    if (threadIdx.x < NUM_OUT) sAll[OFF_B2 + threadIdx.x] = pk2(b2[threadIdx.x], b2[threadIdx.x]);

    int pair = blockIdx.x * blockDim.x + threadIdx.x;
    long e0 = (long)pair * 2;
    bool active = (e0 < E);
    long ee0 = active ? e0 : 0;
    long ee1 = (e0 + 1 < E) ? (e0 + 1) : ee0;

    // ---- Gather inputs (global loads, overlapped with smem weight fill) ----
    const float4* ad4 = reinterpret_cast<const float4*>(a_data);
    const float4* bd4 = reinterpret_cast<const float4*>(b_data);
    const float4* ed4 = reinterpret_cast<const float4*>(e_data);

    u64 xv[NUM_IN];
    xv[0] = pk2(r[ee0], r[ee1]);
    {
        float4 p = ad4[2 * ee0], q = ad4[2 * ee1];
        xv[1] = pk2(p.x, q.x); xv[2] = pk2(p.y, q.y);
        xv[3] = pk2(p.z, q.z); xv[4] = pk2(p.w, q.w);
        p = ad4[2 * ee0 + 1];  q = ad4[2 * ee1 + 1];
        xv[5] = pk2(p.x, q.x); xv[6] = pk2(p.y, q.y);
        xv[7] = pk2(p.z, q.z); xv[8] = pk2(p.w, q.w);
    }
    xv[9]  = pk2(a_material[ee0], a_material[ee1]);
    xv[10] = pk2(a_influx[ee0],   a_influx[ee1]);
    {
        float4 p = bd4[2 * ee0], q = bd4[2 * ee1];
        xv[11] = pk2(p.x, q.x); xv[12] = pk2(p.y, q.y);
        xv[13] = pk2(p.z, q.z); xv[14] = pk2(p.w, q.w);
        p = bd4[2 * ee0 + 1];  q = bd4[2 * ee1 + 1];
        xv[15] = pk2(p.x, q.x); xv[16] = pk2(p.y, q.y);
        xv[17] = pk2(p.z, q.z); xv[18] = pk2(p.w, q.w);
    }
    xv[19] = pk2(b_material[ee0], b_material[ee1]);
    xv[20] = pk2(b_influx[ee0],   b_influx[ee1]);
    {
        float4 p = ed4[ee0], q = ed4[ee1];
        xv[21] = pk2(p.x, q.x); xv[22] = pk2(p.y, q.y);
        xv[23] = pk2(p.z, q.z); xv[24] = pk2(p.w, q.w);
    }

    __syncthreads();

    // ---- Layer 1 in two j-chunks to cap live registers ----
    u64 y[NUM_IN];
    layer1_chunk<0, 13>(sAll, xv, y);
    layer1_chunk<13, 25>(sAll, xv, y);

    if (!active) return;
    bool have_e1 = (e0 + 1 < E);

    // ---- Layer 2 in three i-chunks matching the output blocks ----
    float4* ov = reinterpret_cast<float4*>(out);
    long Ef4_b1 = 2L * (long)E;
    long Ef4_b2 = 4L * (long)E;

    {   // rows 0..7 -> output block 0
        float zl[8], zh[8];
        layer2_chunk<0, 8>(sAll, y, zl, zh);
        ov[2 * e0]     = make_float4(zl[0], zl[1], zl[2], zl[3]);
        ov[2 * e0 + 1] = make_float4(zl[4], zl[5], zl[6], zl[7]);
        if (have_e1) {
            ov[2 * (e0 + 1)]     = make_float4(zh[0], zh[1], zh[2], zh[3]);
            ov[2 * (e0 + 1) + 1] = make_float4(zh[4], zh[5], zh[6], zh[7]);
        }
    }
    {   // rows 8..15 -> output block 1
        float zl[8], zh[8];
        layer2_chunk<8, 16>(sAll, y, zl, zh);
        ov[Ef4_b1 + 2 * e0]     = make_float4(zl[0], zl[1], zl[2], zl[3]);
        ov[Ef4_b1 + 2 * e0 + 1] = make_float4(zl[4], zl[5], zl[6], zl[7]);
        if (have_e1) {
            ov[Ef4_b1 + 2 * (e0 + 1)]     = make_float4(zh[0], zh[1], zh[2], zh[3]);
            ov[Ef4_b1 + 2 * (e0 + 1) + 1] = make_float4(zh[4], zh[5], zh[6], zh[7]);
        }
    }
    {   // rows 16..19 -> output block 2
        float zl[4], zh[4];
        layer2_chunk<16, 20>(sAll, y, zl, zh);
        ov[Ef4_b2 + e0] = make_float4(zl[0], zl[1], zl[2], zl[3]);
        if (have_e1)
            ov[Ef4_b2 + (e0 + 1)] = make_float4(zh[0], zh[1], zh[2], zh[3]);
    }
}

extern "C" void kernel_launch(void* const* d_in, const int* in_sizes, int n_in,
                              void* d_out, int out_size)
{
    const float* r          = (const float*)d_in[0];
    const float* a_data     = (const float*)d_in[1];
    const float* a_material = (const float*)d_in[2];
    const float* a_influx   = (const float*)d_in[3];
    const float* b_data     = (const float*)d_in[4];
    const float* b_material = (const float*)d_in[5];
    const float* b_influx   = (const float*)d_in[6];
    const float* e_data     = (const float*)d_in[7];
    const float* W1         = (const float*)d_in[8];
    const float* b1         = (const float*)d_in[9];
    const float* W2         = (const float*)d_in[10];
    const float* b2         = (const float*)d_in[11];
    float* out = (float*)d_out;

    int E = in_sizes[0];
    int pairs = (E + 1) / 2;
    int threads = 256;
    int blocks = (pairs + threads - 1) / threads;

    edge_mlp_kernel<<<blocks, threads>>>(r, a_data, a_material, a_influx,
                                         b_data, b_material, b_influx, e_data,
                                         W1, b1, W2, b2, out, E);
}

// round 3
// speedup vs baseline: 1.5809x; 1.3703x over previous
#include <cuda_runtime.h>
#include <cstdint>

#define NUM_IN 25   // 2*(8+2)+4+1
#define NUM_OUT 20  // 2*8+4
#define J_PAD 26    // layer-1 rows padded to 26 (13 f32x2 pairs)
#define J_PAIRS 13
#define I_PAIRS 10  // layer-2: 20 rows = 10 pairs exactly

typedef unsigned long long u64;

__device__ __forceinline__ u64 pk2(float lo, float hi) {
    u64 r;
    asm("mov.b64 %0, {%1, %2};" : "=l"(r) : "f"(lo), "f"(hi));
    return r;
}
__device__ __forceinline__ void upk2(u64 v, float& lo, float& hi) {
    asm("mov.b64 {%0, %1}, %2;" : "=f"(lo), "=f"(hi) : "l"(v));
}
__device__ __forceinline__ u64 ffma2(u64 a, u64 b, u64 c) {
    u64 d;
    asm("fma.rn.f32x2 %0, %1, %2, %3;" : "=l"(d) : "l"(a), "l"(b), "l"(c));
    return d;
}

// Shared layout in floats (transposed, k-major, rows 8B-aligned):
//   sW1T: k=0..24, each row 26 floats (j=0..24 real, j=25 zero)   [0, 650)
//   sB1 : 26 floats (j=25 zero)                                   [650, 676)
//   sW2T: k=0..24, each row 20 floats                             [676, 1176)
//   sB2 : 20 floats                                               [1176, 1196)
#define OFF_W1T 0
#define OFF_B1  650
#define OFF_W2T 676
#define OFF_B2  1176
#define SMEM_FLOATS 1196

__global__ void __launch_bounds__(128, 3)
edge_mlp_kernel(const float* __restrict__ r,
                const float* __restrict__ a_data,
                const float* __restrict__ a_material,
                const float* __restrict__ a_influx,
                const float* __restrict__ b_data,
                const float* __restrict__ b_material,
                const float* __restrict__ b_influx,
                const float* __restrict__ e_data,
                const float* __restrict__ W1,
                const float* __restrict__ b1,
                const float* __restrict__ W2,
                const float* __restrict__ b2,
                float* __restrict__ out,
                int E)
{
    __shared__ __align__(16) float sAll[SMEM_FLOATS];

    // ---- Cooperative transpose-load of weights into shared ----
    for (int i = threadIdx.x; i < 25 * J_PAD; i += blockDim.x) {
        int k = i / J_PAD, j = i % J_PAD;
        sAll[OFF_W1T + i] = (j < NUM_IN) ? W1[j * NUM_IN + k] : 0.0f;
    }
    for (int i = threadIdx.x; i < 25 * NUM_OUT; i += blockDim.x) {
        int k = i / NUM_OUT, jj = i % NUM_OUT;
        sAll[OFF_W2T + i] = W2[jj * NUM_IN + k];
    }
    if (threadIdx.x < J_PAD)
        sAll[OFF_B1 + threadIdx.x] = (threadIdx.x < NUM_IN) ? b1[threadIdx.x] : 0.0f;
    if (threadIdx.x < NUM_OUT)
        sAll[OFF_B2 + threadIdx.x] = b2[threadIdx.x];

    long pair = (long)blockIdx.x * blockDim.x + threadIdx.x;
    long e0 = pair * 2;
    bool active = (e0 < E);
    long ee0 = active ? e0 : 0;
    bool have_e1 = (e0 + 1 < E);
    long ee1 = have_e1 ? (e0 + 1) : ee0;

    // ---- Gather inputs as scalar floats for both edges ----
    const float4* ad4 = reinterpret_cast<const float4*>(a_data);
    const float4* bd4 = reinterpret_cast<const float4*>(b_data);
    const float4* ed4 = reinterpret_cast<const float4*>(e_data);

    float x0[NUM_IN], x1[NUM_IN];
    x0[0] = r[ee0]; x1[0] = r[ee1];
    {
        float4 p = ad4[2 * ee0], q = ad4[2 * ee1];
        x0[1] = p.x; x0[2] = p.y; x0[3] = p.z; x0[4] = p.w;
        x1[1] = q.x; x1[2] = q.y; x1[3] = q.z; x1[4] = q.w;
        p = ad4[2 * ee0 + 1]; q = ad4[2 * ee1 + 1];
        x0[5] = p.x; x0[6] = p.y; x0[7] = p.z; x0[8] = p.w;
        x1[5] = q.x; x1[6] = q.y; x1[7] = q.z; x1[8] = q.w;
    }
    x0[9]  = a_material[ee0]; x1[9]  = a_material[ee1];
    x0[10] = a_influx[ee0];   x1[10] = a_influx[ee1];
    {
        float4 p = bd4[2 * ee0], q = bd4[2 * ee1];
        x0[11] = p.x; x0[12] = p.y; x0[13] = p.z; x0[14] = p.w;
        x1[11] = q.x; x1[12] = q.y; x1[13] = q.z; x1[14] = q.w;
        p = bd4[2 * ee0 + 1]; q = bd4[2 * ee1 + 1];
        x0[15] = p.x; x0[16] = p.y; x0[17] = p.z; x0[18] = p.w;
        x1[15] = q.x; x1[16] = q.y; x1[17] = q.z; x1[18] = q.w;
    }
    x0[19] = b_material[ee0]; x1[19] = b_material[ee1];
    x0[20] = b_influx[ee0];   x1[20] = b_influx[ee1];
    {
        float4 p = ed4[ee0], q = ed4[ee1];
        x0[21] = p.x; x0[22] = p.y; x0[23] = p.z; x0[24] = p.w;
        x1[21] = q.x; x1[22] = q.y; x1[23] = q.z; x1[24] = q.w;
    }

    __syncthreads();

    // ---- Layer 1: acc packed over row pairs {j, j+1}; one weight LDS.64
    //      feeds both edges. y kept as scalar floats for layer-2 splats. ----
    u64 acc0[J_PAIRS], acc1[J_PAIRS];
    {
        const u64* sB1p = reinterpret_cast<const u64*>(sAll + OFF_B1);
        #pragma unroll
        for (int jp = 0; jp < J_PAIRS; jp++) { acc0[jp] = sB1p[jp]; acc1[jp] = sB1p[jp]; }
    }
    #pragma unroll
    for (int k = 0; k < NUM_IN; k++) {
        const u64* wrow = reinterpret_cast<const u64*>(sAll + OFF_W1T + k * J_PAD);
        u64 xk0 = pk2(x0[k], x0[k]);
        u64 xk1 = pk2(x1[k], x1[k]);
        #pragma unroll
        for (int jp = 0; jp < J_PAIRS; jp++) {
            u64 w = wrow[jp];
            acc0[jp] = ffma2(w, xk0, acc0[jp]);
            acc1[jp] = ffma2(w, xk1, acc1[jp]);
        }
    }

    float y0[J_PAD], y1[J_PAD];
    #pragma unroll
    for (int jp = 0; jp < J_PAIRS; jp++) {
        float lo, hi;
        upk2(acc0[jp], lo, hi);
        y0[2 * jp]     = fmaxf(lo, 0.0f);
        y0[2 * jp + 1] = fmaxf(hi, 0.0f);
        upk2(acc1[jp], lo, hi);
        y1[2 * jp]     = fmaxf(lo, 0.0f);
        y1[2 * jp + 1] = fmaxf(hi, 0.0f);
    }

    // ---- Layer 2: 20 rows = 10 pairs, same sharing scheme ----
    u64 z0[I_PAIRS], z1[I_PAIRS];
    {
        const u64* sB2p = reinterpret_cast<const u64*>(sAll + OFF_B2);
        #pragma unroll
        for (int ip = 0; ip < I_PAIRS; ip++) { z0[ip] = sB2p[ip]; z1[ip] = sB2p[ip]; }
    }
    #pragma unroll
    for (int k = 0; k < NUM_IN; k++) {
        const u64* wrow = reinterpret_cast<const u64*>(sAll + OFF_W2T + k * NUM_OUT);
        u64 yk0 = pk2(y0[k], y0[k]);
        u64 yk1 = pk2(y1[k], y1[k]);
        #pragma unroll
        for (int ip = 0; ip < I_PAIRS; ip++) {
            u64 w = wrow[ip];
            z0[ip] = ffma2(w, yk0, z0[ip]);
            z1[ip] = ffma2(w, yk1, z1[ip]);
        }
    }

    if (!active) return;

    float zl[NUM_OUT], zh[NUM_OUT];
    #pragma unroll
    for (int ip = 0; ip < I_PAIRS; ip++) {
        float lo, hi;
        upk2(z0[ip], lo, hi);
        zl[2 * ip]     = fmaxf(lo, 0.0f);
        zl[2 * ip + 1] = fmaxf(hi, 0.0f);
        upk2(z1[ip], lo, hi);
        zh[2 * ip]     = fmaxf(lo, 0.0f);
        zh[2 * ip + 1] = fmaxf(hi, 0.0f);
    }

    // ---- Scatter to the three concatenated output blocks ----
    float4* ov = reinterpret_cast<float4*>(out);
    long Ef4_b1 = 2L * (long)E;
    long Ef4_b2 = 4L * (long)E;

    ov[2 * e0]              = make_float4(zl[0],  zl[1],  zl[2],  zl[3]);
    ov[2 * e0 + 1]          = make_float4(zl[4],  zl[5],  zl[6],  zl[7]);
    ov[Ef4_b1 + 2 * e0]     = make_float4(zl[8],  zl[9],  zl[10], zl[11]);
    ov[Ef4_b1 + 2 * e0 + 1] = make_float4(zl[12], zl[13], zl[14], zl[15]);
    ov[Ef4_b2 + e0]         = make_float4(zl[16], zl[17], zl[18], zl[19]);

    if (have_e1) {
        long e1 = e0 + 1;
        ov[2 * e1]              = make_float4(zh[0],  zh[1],  zh[2],  zh[3]);
        ov[2 * e1 + 1]          = make_float4(zh[4],  zh[5],  zh[6],  zh[7]);
        ov[Ef4_b1 + 2 * e1]     = make_float4(zh[8],  zh[9],  zh[10], zh[11]);
        ov[Ef4_b1 + 2 * e1 + 1] = make_float4(zh[12], zh[13], zh[14], zh[15]);
        ov[Ef4_b2 + e1]         = make_float4(zh[16], zh[17], zh[18], zh[19]);
    }
}

extern "C" void kernel_launch(void* const* d_in, const int* in_sizes, int n_in,
                              void* d_out, int out_size)
{
    const float* r          = (const float*)d_in[0];
    const float* a_data     = (const float*)d_in[1];
    const float* a_material = (const float*)d_in[2];
    const float* a_influx   = (const float*)d_in[3];
    const float* b_data     = (const float*)d_in[4];
    const float* b_material = (const float*)d_in[5];
    const float* b_influx   = (const float*)d_in[6];
    const float* e_data     = (const float*)d_in[7];
    const float* W1         = (const float*)d_in[8];
    const float* b1         = (const float*)d_in[9];
    const float* W2         = (const float*)d_in[10];
    const float* b2         = (const float*)d_in[11];
    float* out = (float*)d_out;

    int E = in_sizes[0];
    long pairs = ((long)E + 1) / 2;
    int threads = 128;
    int blocks = (int)((pairs + threads - 1) / threads);

    edge_mlp_kernel<<<blocks, threads>>>(r, a_data, a_material, a_influx,
                                         b_data, b_material, b_influx, e_data,
                                         W1, b1, W2, b2, out, E);
}